// round 2
// baseline (speedup 1.0000x reference)
#include <cuda_runtime.h>

#define BB   8
#define CC   64
#define HH   128
#define WW   128
#define COUT 64
#define K2   9
#define HWSZ (HH*WW)        /* 16384 */
#define NPIX (BB*HWSZ)      /* 131072 */
#define PT   32             /* pixel tile per block */
#define NR   288            /* col rows = K2*32 channel-pairs */
#define PITCH 66            /* 2*PT + 2 pad (odd in 64b units -> conflict-free STS.64) */

typedef unsigned long long u64;

// scratch (allocation-free rule: __device__ globals)
__device__ __align__(16) float g_xt[(size_t)NPIX * CC];   // x transposed to NHWC, 33.5 MB
__device__ __align__(16) float g_wt[NR * COUT * 2];       // weights packed as channel pairs

__device__ __forceinline__ u64 fma2(u64 a, u64 b, u64 c) {
    u64 d;
    asm("fma.rn.f32x2 %0, %1, %2, %3;" : "=l"(d) : "l"(a), "l"(b), "l"(c));
    return d;
}
__device__ __forceinline__ float lo32(u64 v) { return __uint_as_float((unsigned)v); }
__device__ __forceinline__ float hi32(u64 v) { return __uint_as_float((unsigned)(v >> 32)); }

// ---------------- kernel 1: NCHW -> NHWC transpose of x ----------------
__global__ __launch_bounds__(256) void k_transpose_x(const float* __restrict__ x) {
    __shared__ float s[64][33];
    const int tile = blockIdx.x;           // 4096 tiles of 32 pixels
    const int px0  = tile * 32;            // global pixel index (b*16384 + pix)
    const int b    = px0 >> 14;
    const int pix0 = px0 & 16383;
    const int t    = threadIdx.x;
    const int lane = t & 31;
    const int cg   = t >> 5;               // 8 warps
    #pragma unroll
    for (int cc = cg; cc < 64; cc += 8)
        s[cc][lane] = x[((size_t)(b * 64 + cc)) * HWSZ + pix0 + lane];
    __syncthreads();
    #pragma unroll
    for (int i = t; i < 2048; i += 256) {
        int c = i & 63;
        int p = i >> 6;
        g_xt[((size_t)(px0 + p)) * CC + c] = s[c][p];
    }
}

// ---------------- kernel 2: pack weights as channel pairs ----------------
// g_wt[(r*64 + o)*2 + j] = weight[o][c][ky][kx],  c = 2*(r%32)+j, k = r/32 = ky*3+kx
__global__ __launch_bounds__(256) void k_prep_w(const float* __restrict__ w) {
    int i = blockIdx.x * 256 + threadIdx.x;
    if (i < NR * COUT * 2) {
        int j = i & 1;
        int o = (i >> 1) & 63;
        int r = i >> 7;
        int c = 2 * (r & 31) + j;
        int k = r >> 5;
        g_wt[i] = w[(o * 64 + c) * 9 + k];
    }
}

// ---------------- kernel 3: fused sampling + GEMM ----------------
__global__ __launch_bounds__(128) void k_dcn_main(
    const float* __restrict__ offset, const float* __restrict__ mask,
    const float* __restrict__ bias, float* __restrict__ out)
{
    extern __shared__ float col_s[];       // [NR][PITCH]
    const int t    = threadIdx.x;
    const int lane = t & 31;
    const int warp = t >> 5;
    const int blk  = blockIdx.x;
    const int w0   = (blk & 3) * PT;
    const int h    = (blk >> 2) & 127;
    const int b    = blk >> 9;

    // ---- phase 1: bilinear-sample 32 px x 9 taps into smem (warp-wide tasks) ----
    const float* xb = g_xt + (size_t)b * HWSZ * CC + lane * 2;
    for (int task = warp; task < NR; task += 4) {
        const int k  = task >> 5;
        const int p  = task & 31;
        const int wq = w0 + p;
        const float* offp = offset + (((size_t)b * 18 + 2 * k) * HH + h) * WW + wq;
        const float dx = offp[0];
        const float dy = offp[HWSZ];
        const float m  = mask[(((size_t)b * 9 + k) * HH + h) * WW + wq];
        const float py = (float)(h  - 1 + k / 3) + dy;
        const float px = (float)(wq - 1 + k % 3) + dx;
        const float y0f = floorf(py), x0f = floorf(px);
        const float wy1 = py - y0f,  wx1 = px - x0f;
        const float wy0 = 1.f - wy1, wx0 = 1.f - wx1;
        const int y0 = (int)y0f, x0 = (int)x0f;
        const int y1 = y0 + 1,   x1 = x0 + 1;
        const bool vy0 = (unsigned)y0 < 128u, vy1 = (unsigned)y1 < 128u;
        const bool vx0 = (unsigned)x0 < 128u, vx1 = (unsigned)x1 < 128u;
        const float2 z = make_float2(0.f, 0.f);
        float2 v00 = (vy0 && vx0) ? *(const float2*)(xb + (y0 * WW + x0) * CC) : z;
        float2 v01 = (vy0 && vx1) ? *(const float2*)(xb + (y0 * WW + x1) * CC) : z;
        float2 v10 = (vy1 && vx0) ? *(const float2*)(xb + (y1 * WW + x0) * CC) : z;
        float2 v11 = (vy1 && vx1) ? *(const float2*)(xb + (y1 * WW + x1) * CC) : z;
        const float a00 = m * wy0 * wx0, a01 = m * wy0 * wx1;
        const float a10 = m * wy1 * wx0, a11 = m * wy1 * wx1;
        float2 val;
        val.x = a00 * v00.x + a01 * v01.x + a10 * v10.x + a11 * v11.x;
        val.y = a00 * v00.y + a01 * v01.y + a10 * v10.y + a11 * v11.y;
        *(float2*)&col_s[(k * 32 + lane) * PITCH + 2 * p] = val;   // STS.64, lane stride 66 words -> conflict-free
    }
    __syncthreads();

    // ---- phase 2: register-tiled GEMM, f32x2 over channel pairs ----
    const int p0 = (t & 7) * 4;        // 8 groups x 4 px  = 32 px
    const int o0 = (t >> 3) * 4;       // 16 groups x 4 out = 64 out
    u64 acc[4][4];
    #pragma unroll
    for (int i = 0; i < 4; i++)
        #pragma unroll
        for (int j = 0; j < 4; j++) acc[i][j] = 0ull;

    const u64* wt64 = (const u64*)g_wt;   // wt64[r*64 + o] = packed (w_c0, w_c1)
    #pragma unroll 2
    for (int r = 0; r < NR; r++) {
        const float* cs = &col_s[r * PITCH + 2 * p0];
        u64 c0 = *(const u64*)(cs + 0);
        u64 c1 = *(const u64*)(cs + 2);
        u64 c2 = *(const u64*)(cs + 4);
        u64 c3 = *(const u64*)(cs + 6);
        const ulonglong2* wp = (const ulonglong2*)(wt64 + r * 64 + o0);
        ulonglong2 wA = wp[0];   // outs o0, o0+1
        ulonglong2 wB = wp[1];   // outs o0+2, o0+3
        acc[0][0] = fma2(c0, wA.x, acc[0][0]);
        acc[1][0] = fma2(c1, wA.x, acc[1][0]);
        acc[2][0] = fma2(c2, wA.x, acc[2][0]);
        acc[3][0] = fma2(c3, wA.x, acc[3][0]);
        acc[0][1] = fma2(c0, wA.y, acc[0][1]);
        acc[1][1] = fma2(c1, wA.y, acc[1][1]);
        acc[2][1] = fma2(c2, wA.y, acc[2][1]);
        acc[3][1] = fma2(c3, wA.y, acc[3][1]);
        acc[0][2] = fma2(c0, wB.x, acc[0][2]);
        acc[1][2] = fma2(c1, wB.x, acc[1][2]);
        acc[2][2] = fma2(c2, wB.x, acc[2][2]);
        acc[3][2] = fma2(c3, wB.x, acc[3][2]);
        acc[0][3] = fma2(c0, wB.y, acc[0][3]);
        acc[1][3] = fma2(c1, wB.y, acc[1][3]);
        acc[2][3] = fma2(c2, wB.y, acc[2][3]);
        acc[3][3] = fma2(c3, wB.y, acc[3][3]);
    }

    // ---- epilogue: reduce channel halves, add bias, vector store ----
    #pragma unroll
    for (int oi = 0; oi < 4; oi++) {
        const int o = o0 + oi;
        const float bo = bias[o];
        float4 res;
        res.x = lo32(acc[0][oi]) + hi32(acc[0][oi]) + bo;
        res.y = lo32(acc[1][oi]) + hi32(acc[1][oi]) + bo;
        res.z = lo32(acc[2][oi]) + hi32(acc[2][oi]) + bo;
        res.w = lo32(acc[3][oi]) + hi32(acc[3][oi]) + bo;
        *(float4*)(out + (((size_t)b * COUT + o) * HH + h) * WW + w0 + p0) = res;
    }
}

extern "C" void kernel_launch(void* const* d_in, const int* in_sizes, int n_in,
                              void* d_out, int out_size) {
    const float* x      = (const float*)d_in[0];
    const float* offset = (const float*)d_in[1];
    const float* mask   = (const float*)d_in[2];
    const float* weight = (const float*)d_in[3];
    const float* bias   = (const float*)d_in[4];
    float* out = (float*)d_out;

    const int smem = NR * PITCH * (int)sizeof(float);  // 76032 B
    cudaFuncSetAttribute(k_dcn_main, cudaFuncAttributeMaxDynamicSharedMemorySize, smem);

    k_transpose_x<<<NPIX / 32, 256>>>(x);
    k_prep_w<<<(NR * COUT * 2 + 255) / 256, 256>>>(weight);
    k_dcn_main<<<BB * HH * (WW / PT), 128, smem>>>(offset, mask, bias, out);
}

// round 3
// speedup vs baseline: 1.0585x; 1.0585x over previous
#include <cuda_runtime.h>

#define BB   8
#define CC   64
#define HH   128
#define WW   128
#define COUT 64
#define K2   9
#define HWSZ (HH*WW)        /* 16384 */
#define NPIX (BB*HWSZ)      /* 131072 */
#define PT   32             /* pixel tile per block */
#define NR   288            /* col rows = K2*32 channel-pairs */
#define PITCH 66            /* 2*PT + 2 pad */
#define WS   48             /* weight rows staged per chunk */
#define NSTG 6              /* 288/48 */

typedef unsigned long long u64;

// scratch (allocation-free rule: __device__ globals)
__device__ __align__(16) float g_xt[(size_t)NPIX * CC];   // x transposed to NHWC, 33.5 MB
__device__ __align__(16) float g_wt[NR * COUT * 2];       // weights packed as channel pairs (144 KB)

__device__ __forceinline__ u64 fma2(u64 a, u64 b, u64 c) {
    u64 d;
    asm("fma.rn.f32x2 %0, %1, %2, %3;" : "=l"(d) : "l"(a), "l"(b), "l"(c));
    return d;
}
__device__ __forceinline__ float lo32(u64 v) { return __uint_as_float((unsigned)v); }
__device__ __forceinline__ float hi32(u64 v) { return __uint_as_float((unsigned)(v >> 32)); }

// ---------------- kernel 1: NCHW -> NHWC transpose of x ----------------
__global__ __launch_bounds__(256) void k_transpose_x(const float* __restrict__ x) {
    __shared__ float s[64][33];
    const int tile = blockIdx.x;
    const int px0  = tile * 32;
    const int b    = px0 >> 14;
    const int pix0 = px0 & 16383;
    const int t    = threadIdx.x;
    const int lane = t & 31;
    const int cg   = t >> 5;
    #pragma unroll
    for (int cc = cg; cc < 64; cc += 8)
        s[cc][lane] = x[((size_t)(b * 64 + cc)) * HWSZ + pix0 + lane];
    __syncthreads();
    #pragma unroll
    for (int i = t; i < 2048; i += 256) {
        int c = i & 63;
        int p = i >> 6;
        g_xt[((size_t)(px0 + p)) * CC + c] = s[c][p];
    }
}

// ---------------- kernel 2: pack weights as channel pairs ----------------
// g_wt[(r*64 + o)*2 + j] = weight[o][c][k],  c = 2*(r%32)+j, k = r/32
__global__ __launch_bounds__(256) void k_prep_w(const float* __restrict__ w) {
    int i = blockIdx.x * 256 + threadIdx.x;
    if (i < NR * COUT * 2) {
        int j = i & 1;
        int o = (i >> 1) & 63;
        int r = i >> 7;
        int c = 2 * (r & 31) + j;
        int k = r >> 5;
        g_wt[i] = w[(o * 64 + c) * 9 + k];
    }
}

// ---------------- kernel 3: fused sampling + GEMM (weights staged in smem) ----------------
__global__ __launch_bounds__(128, 2) void k_dcn_main(
    const float* __restrict__ offset, const float* __restrict__ mask,
    const float* __restrict__ bias, float* __restrict__ out)
{
    extern __shared__ float smem[];
    float* col_s = smem;                       // [NR][PITCH]  = 19008 floats
    float* w_s   = smem + NR * PITCH;          // [WS][128]    =  6144 floats
    const int t    = threadIdx.x;
    const int lane = t & 31;
    const int warp = t >> 5;
    const int blk  = blockIdx.x;
    const int w0   = (blk & 3) * PT;
    const int h    = (blk >> 2) & 127;
    const int b    = blk >> 9;

    // ---- prefetch weight stage 0 into smem (overlaps with sampling) ----
    {
        const float4* src = (const float4*)g_wt;
        float4* dst = (float4*)w_s;
        #pragma unroll
        for (int i = 0; i < 12; i++)
            dst[t + i * 128] = src[t + i * 128];
    }

    // ---- phase 1: bilinear-sample 32 px x 9 taps into smem (warp-wide tasks) ----
    const float* xb = g_xt + (size_t)b * HWSZ * CC + lane * 2;
    #pragma unroll 2
    for (int task = warp; task < NR; task += 4) {
        const int k  = task >> 5;
        const int p  = task & 31;
        const int wq = w0 + p;
        const float* offp = offset + (((size_t)b * 18 + 2 * k) * HH + h) * WW + wq;
        const float dx = offp[0];
        const float dy = offp[HWSZ];
        const float m  = mask[(((size_t)b * 9 + k) * HH + h) * WW + wq];
        const float py = (float)(h  - 1 + k / 3) + dy;
        const float px = (float)(wq - 1 + k % 3) + dx;
        const float y0f = floorf(py), x0f = floorf(px);
        const float wy1 = py - y0f,  wx1 = px - x0f;
        const float wy0 = 1.f - wy1, wx0 = 1.f - wx1;
        const int y0 = (int)y0f, x0 = (int)x0f;
        const int y1 = y0 + 1,   x1 = x0 + 1;
        const bool vy0 = (unsigned)y0 < 128u, vy1 = (unsigned)y1 < 128u;
        const bool vx0 = (unsigned)x0 < 128u, vx1 = (unsigned)x1 < 128u;
        const float2 z = make_float2(0.f, 0.f);
        float2 v00 = (vy0 && vx0) ? *(const float2*)(xb + (y0 * WW + x0) * CC) : z;
        float2 v01 = (vy0 && vx1) ? *(const float2*)(xb + (y0 * WW + x1) * CC) : z;
        float2 v10 = (vy1 && vx0) ? *(const float2*)(xb + (y1 * WW + x0) * CC) : z;
        float2 v11 = (vy1 && vx1) ? *(const float2*)(xb + (y1 * WW + x1) * CC) : z;
        const float a00 = m * wy0 * wx0, a01 = m * wy0 * wx1;
        const float a10 = m * wy1 * wx0, a11 = m * wy1 * wx1;
        float2 val;
        val.x = a00 * v00.x + a01 * v01.x + a10 * v10.x + a11 * v11.x;
        val.y = a00 * v00.y + a01 * v01.y + a10 * v10.y + a11 * v11.y;
        *(float2*)&col_s[(k * 32 + lane) * PITCH + 2 * p] = val;
    }
    __syncthreads();

    // ---- phase 2: register-tiled GEMM, all operands from smem ----
    const int p0 = (t & 7) * 4;        // 8 groups x 4 px  = 32 px
    const int o0 = (t >> 3) * 4;       // 16 groups x 4 out = 64 out
    u64 acc[4][4];
    #pragma unroll
    for (int i = 0; i < 4; i++)
        #pragma unroll
        for (int j = 0; j < 4; j++) acc[i][j] = 0ull;

    for (int st = 0; st < NSTG; st++) {
        const u64* ws64 = (const u64*)w_s;
        const float* cbase = &col_s[st * WS * PITCH + 2 * p0];
        #pragma unroll 4
        for (int rr = 0; rr < WS; rr++) {
            const float* cs = cbase + rr * PITCH;
            u64 c0 = *(const u64*)(cs + 0);
            u64 c1 = *(const u64*)(cs + 2);
            u64 c2 = *(const u64*)(cs + 4);
            u64 c3 = *(const u64*)(cs + 6);
            const ulonglong2* wp = (const ulonglong2*)(ws64 + rr * 64 + o0);
            ulonglong2 wA = wp[0];
            ulonglong2 wB = wp[1];
            acc[0][0] = fma2(c0, wA.x, acc[0][0]);
            acc[1][0] = fma2(c1, wA.x, acc[1][0]);
            acc[2][0] = fma2(c2, wA.x, acc[2][0]);
            acc[3][0] = fma2(c3, wA.x, acc[3][0]);
            acc[0][1] = fma2(c0, wA.y, acc[0][1]);
            acc[1][1] = fma2(c1, wA.y, acc[1][1]);
            acc[2][1] = fma2(c2, wA.y, acc[2][1]);
            acc[3][1] = fma2(c3, wA.y, acc[3][1]);
            acc[0][2] = fma2(c0, wB.x, acc[0][2]);
            acc[1][2] = fma2(c1, wB.x, acc[1][2]);
            acc[2][2] = fma2(c2, wB.x, acc[2][2]);
            acc[3][2] = fma2(c3, wB.x, acc[3][2]);
            acc[0][3] = fma2(c0, wB.y, acc[0][3]);
            acc[1][3] = fma2(c1, wB.y, acc[1][3]);
            acc[2][3] = fma2(c2, wB.y, acc[2][3]);
            acc[3][3] = fma2(c3, wB.y, acc[3][3]);
        }
        if (st + 1 < NSTG) {
            __syncthreads();           // all readers of this stage done
            const float4* src = (const float4*)(g_wt + (size_t)(st + 1) * WS * 128);
            float4* dst = (float4*)w_s;
            #pragma unroll
            for (int i = 0; i < 12; i++)
                dst[t + i * 128] = src[t + i * 128];
            __syncthreads();           // new stage visible
        }
    }

    // ---- epilogue: reduce channel halves, add bias, vector store ----
    #pragma unroll
    for (int oi = 0; oi < 4; oi++) {
        const int o = o0 + oi;
        const float bo = bias[o];
        float4 res;
        res.x = lo32(acc[0][oi]) + hi32(acc[0][oi]) + bo;
        res.y = lo32(acc[1][oi]) + hi32(acc[1][oi]) + bo;
        res.z = lo32(acc[2][oi]) + hi32(acc[2][oi]) + bo;
        res.w = lo32(acc[3][oi]) + hi32(acc[3][oi]) + bo;
        *(float4*)(out + (((size_t)b * COUT + o) * HH + h) * WW + w0 + p0) = res;
    }
}

extern "C" void kernel_launch(void* const* d_in, const int* in_sizes, int n_in,
                              void* d_out, int out_size) {
    const float* x      = (const float*)d_in[0];
    const float* offset = (const float*)d_in[1];
    const float* mask   = (const float*)d_in[2];
    const float* weight = (const float*)d_in[3];
    const float* bias   = (const float*)d_in[4];
    float* out = (float*)d_out;

    const int smem = (NR * PITCH + WS * 128) * (int)sizeof(float);  // 100608 B
    cudaFuncSetAttribute(k_dcn_main, cudaFuncAttributeMaxDynamicSharedMemorySize, smem);

    k_transpose_x<<<NPIX / 32, 256>>>(x);
    k_prep_w<<<(NR * COUT * 2 + 255) / 256, 256>>>(weight);
    k_dcn_main<<<BB * HH * (WW / PT), 128, smem>>>(offset, mask, bias, out);
}

// round 5
// speedup vs baseline: 2.0783x; 1.9635x over previous
#include <cuda_runtime.h>

#define BB   8
#define CC   64
#define HH   128
#define WW   128
#define COUT 64
#define K2   9
#define HWSZ (HH*WW)        /* 16384 */
#define NPIX (BB*HWSZ)      /* 131072 */
#define PT   64             /* pixel tile per block */
#define PITCH 130           /* 2*PT + 2 pad */
#define CBUF (32*PITCH)     /* 4160 floats per col buffer */
#define WBUF 4096           /* floats per weight buffer (32 rows x 128) */
#define WOFF (2*CBUF)       /* 8320 */

typedef unsigned long long u64;

// scratch (allocation-free rule: __device__ globals)
__device__ __align__(16) float g_xt[(size_t)NPIX * CC];   // x in NHWC, 33.5 MB
__device__ __align__(16) float g_wt[K2 * 32 * COUT * 2];  // weights packed: [k*32+pair][o][2]

__device__ __forceinline__ u64 fma2(u64 a, u64 b, u64 c) {
    u64 d;
    asm("fma.rn.f32x2 %0, %1, %2, %3;" : "=l"(d) : "l"(a), "l"(b), "l"(c));
    return d;
}
__device__ __forceinline__ float lo32(u64 v) { return __uint_as_float((unsigned)v); }
__device__ __forceinline__ float hi32(u64 v) { return __uint_as_float((unsigned)(v >> 32)); }

__device__ __forceinline__ void cp16(void* s, const void* g) {
    unsigned a = (unsigned)__cvta_generic_to_shared(s);
    asm volatile("cp.async.cg.shared.global [%0], [%1], 16;\n" :: "r"(a), "l"(g) : "memory");
}
#define CP_COMMIT() asm volatile("cp.async.commit_group;\n" ::: "memory")
#define CP_WAIT0()  asm volatile("cp.async.wait_group 0;\n" ::: "memory")

// ---------------- kernel 1: NCHW -> NHWC transpose of x ----------------
__global__ __launch_bounds__(256) void k_transpose_x(const float* __restrict__ x) {
    __shared__ float s[64][33];
    const int tile = blockIdx.x;
    const int px0  = tile * 32;
    const int b    = px0 >> 14;
    const int pix0 = px0 & 16383;
    const int t    = threadIdx.x;
    const int lane = t & 31;
    const int cg   = t >> 5;
    #pragma unroll
    for (int cc = cg; cc < 64; cc += 8)
        s[cc][lane] = x[((size_t)(b * 64 + cc)) * HWSZ + pix0 + lane];
    __syncthreads();
    #pragma unroll
    for (int i = t; i < 2048; i += 256) {
        int c = i & 63;
        int p = i >> 6;
        g_xt[((size_t)(px0 + p)) * CC + c] = s[c][p];
    }
}

// ---------------- kernel 2: pack weights as channel pairs ----------------
__global__ __launch_bounds__(256) void k_prep_w(const float* __restrict__ w) {
    int i = blockIdx.x * 256 + threadIdx.x;
    if (i < K2 * 32 * COUT * 2) {
        int j = i & 1;
        int o = (i >> 1) & 63;
        int r = i >> 7;
        int c = 2 * (r & 31) + j;
        int k = r >> 5;
        g_wt[i] = w[(o * 64 + c) * 9 + k];
    }
}

// ---------------- sampling helpers ----------------
__device__ __forceinline__ void gatherTask(
    float dx, float dy, float m, float kyf, float kxf, int px_coord,
    const float* __restrict__ xb, float2 g[4], float a[4])
{
    const float py  = kyf + dy;
    const float px  = (float)(px_coord - 1) + kxf + dx;
    const float y0f = floorf(py), x0f = floorf(px);
    const float wy1 = py - y0f,  wx1 = px - x0f;
    const float wy0 = 1.f - wy1, wx0 = 1.f - wx1;
    const int iy = (int)y0f, ix = (int)x0f;
    const bool vy0 = (unsigned)iy < (unsigned)HH, vy1 = (unsigned)(iy + 1) < (unsigned)HH;
    const bool vx0 = (unsigned)ix < (unsigned)WW, vx1 = (unsigned)(ix + 1) < (unsigned)WW;
    const float2 z = make_float2(0.f, 0.f);
    const float* bp = xb + ((long)iy * WW + ix) * CC;
    g[0] = (vy0 && vx0) ? *(const float2*)(bp)               : z;
    g[1] = (vy0 && vx1) ? *(const float2*)(bp + CC)          : z;
    g[2] = (vy1 && vx0) ? *(const float2*)(bp + WW * CC)     : z;
    g[3] = (vy1 && vx1) ? *(const float2*)(bp + WW * CC + CC): z;
    a[0] = m * wy0 * wx0;
    a[1] = m * wy0 * wx1;
    a[2] = m * wy1 * wx0;
    a[3] = m * wy1 * wx1;
}

__device__ __forceinline__ void storeTask(
    float* __restrict__ colb, int lane, int plocal, const float2 g[4], const float a[4])
{
    float2 v;
    v.x = a[0] * g[0].x + a[1] * g[1].x + a[2] * g[2].x + a[3] * g[3].x;
    v.y = a[0] * g[0].y + a[1] * g[1].y + a[2] * g[2].y + a[3] * g[3].y;
    *(float2*)(colb + lane * PITCH + 2 * plocal) = v;
}

// ---------------- kernel 3: fused, tap-pipelined ----------------
__global__ __launch_bounds__(256, 2) void k_dcn_main(
    const float* __restrict__ offset, const float* __restrict__ mask,
    const float* __restrict__ bias, float* __restrict__ out)
{
    extern __shared__ float smem[];   // [2*CBUF col | 2*WBUF weights]
    const int t    = threadIdx.x;
    const int lane = t & 31;
    const int warp = t >> 5;          // 0..7
    const int blk  = blockIdx.x;
    const int w0   = (blk & 1) * PT;
    const int h    = (blk >> 1) & 127;
    const int b    = blk >> 8;
    const int pg   = t & 15;          // pixel group: pixels pg + 16*i
    const int o0   = (t >> 4) * 4;    // 4 consecutive outs

    const float* xb      = g_xt + (size_t)b * HWSZ * CC + lane * 2;
    const int    pbase   = w0 + warp * 8;
    const float* offbase = offset + ((size_t)b * 18 * HH + h) * WW + pbase;
    const float* mbase   = mask   + ((size_t)b *  9 * HH + h) * WW + pbase;

    // ---- prologue: stage weights tap0 (cp.async) + sample tap0 ----
    {
        float4* wd4 = (float4*)(smem + WOFF);
        const float4* ws4 = (const float4*)g_wt;
        cp16(wd4 + t, ws4 + t);
        cp16(wd4 + t + 256, ws4 + t + 256);
        cp16(wd4 + t + 512, ws4 + t + 512);
        cp16(wd4 + t + 768, ws4 + t + 768);
        CP_COMMIT();
        const float* offx = offbase;
        const float* offy = offx + HWSZ;
        const float* mk   = mbase;
        const float kyf = (float)(h - 1), kxf = 0.f;
        #pragma unroll
        for (int i = 0; i < 8; i += 2) {
            float2 g0[4], g1[4]; float a0[4], a1[4];
            gatherTask(offx[i],   offy[i],   mk[i],   kyf, kxf, pbase + i,     xb, g0, a0);
            gatherTask(offx[i+1], offy[i+1], mk[i+1], kyf, kxf, pbase + i + 1, xb, g1, a1);
            storeTask(smem, lane, warp * 8 + i,     g0, a0);
            storeTask(smem, lane, warp * 8 + i + 1, g1, a1);
        }
        CP_WAIT0();
        __syncthreads();
    }

    u64 acc[4][4];
    #pragma unroll
    for (int i = 0; i < 4; i++)
        #pragma unroll
        for (int j = 0; j < 4; j++) acc[i][j] = 0ull;

    float dxA[2], dyA[2], mA[2], dxB[2], dyB[2], mB[2];
    float2 gA[8], gB[8];
    float  aA[8], aB[8];

    #pragma unroll 1
    for (int k = 0; k < K2; k++) {
        const int cur = k & 1, nxt = cur ^ 1;
        const bool pre = (k < K2 - 1);
        const float* colc = smem + cur * CBUF + 2 * pg;
        float*       coln = smem + nxt * CBUF;
        const u64*   wb   = (const u64*)(smem + WOFF + cur * WBUF) + o0;

        float kyf = 0.f, kxf = 0.f;
        const float *offx = offbase, *offy = offbase, *mk = mbase;
        if (pre) {
            const int kn  = k + 1;
            const int kny = kn / 3;
            kyf = (float)(h - 1 + kny);
            kxf = (float)(kn - kny * 3);
            offx = offbase + (size_t)(2 * kn) * HWSZ;
            offy = offx + HWSZ;
            mk   = mbase + (size_t)kn * HWSZ;
            // stage next-tap weights, register-free
            float4* wd4 = (float4*)(smem + WOFF + nxt * WBUF);
            const float4* ws4 = (const float4*)(g_wt + (size_t)kn * WBUF);
            cp16(wd4 + t, ws4 + t);
            cp16(wd4 + t + 256, ws4 + t + 256);
            cp16(wd4 + t + 512, ws4 + t + 512);
            cp16(wd4 + t + 768, ws4 + t + 768);
            CP_COMMIT();
            // coords pair A (tasks 0,1)
            dxA[0] = offx[0]; dyA[0] = offy[0]; mA[0] = mk[0];
            dxA[1] = offx[1]; dyA[1] = offy[1]; mA[1] = mk[1];
        }

        #define GEMM_CHUNK(c)                                                   \
        {                                                                       \
            _Pragma("unroll")                                                   \
            for (int rr = 0; rr < 8; rr++) {                                    \
                const int r = (c) * 8 + rr;                                     \
                const float* cs = colc + r * PITCH;                             \
                u64 cc0 = *(const u64*)(cs);                                    \
                u64 cc1 = *(const u64*)(cs + 32);                               \
                u64 cc2 = *(const u64*)(cs + 64);                               \
                u64 cc3 = *(const u64*)(cs + 96);                               \
                ulonglong2 wA = *(const ulonglong2*)(wb + r * 64);              \
                ulonglong2 wB = *(const ulonglong2*)(wb + r * 64 + 2);          \
                acc[0][0] = fma2(cc0, wA.x, acc[0][0]);                         \
                acc[1][0] = fma2(cc1, wA.x, acc[1][0]);                         \
                acc[2][0] = fma2(cc2, wA.x, acc[2][0]);                         \
                acc[3][0] = fma2(cc3, wA.x, acc[3][0]);                         \
                acc[0][1] = fma2(cc0, wA.y, acc[0][1]);                         \
                acc[1][1] = fma2(cc1, wA.y, acc[1][1]);                         \
                acc[2][1] = fma2(cc2, wA.y, acc[2][1]);                         \
                acc[3][1] = fma2(cc3, wA.y, acc[3][1]);                         \
                acc[0][2] = fma2(cc0, wB.x, acc[0][2]);                         \
                acc[1][2] = fma2(cc1, wB.x, acc[1][2]);                         \
                acc[2][2] = fma2(cc2, wB.x, acc[2][2]);                         \
                acc[3][2] = fma2(cc3, wB.x, acc[3][2]);                         \
                acc[0][3] = fma2(cc0, wB.y, acc[0][3]);                         \
                acc[1][3] = fma2(cc1, wB.y, acc[1][3]);                         \
                acc[2][3] = fma2(cc2, wB.y, acc[2][3]);                         \
                acc[3][3] = fma2(cc3, wB.y, acc[3][3]);                         \
            }                                                                   \
        }

        GEMM_CHUNK(0);
        if (pre) {
            gatherTask(dxA[0], dyA[0], mA[0], kyf, kxf, pbase + 0, xb, gA,     aA);
            gatherTask(dxA[1], dyA[1], mA[1], kyf, kxf, pbase + 1, xb, gA + 4, aA + 4);
            dxB[0] = offx[2]; dyB[0] = offy[2]; mB[0] = mk[2];
            dxB[1] = offx[3]; dyB[1] = offy[3]; mB[1] = mk[3];
        }
        GEMM_CHUNK(1);
        if (pre) {
            storeTask(coln, lane, warp * 8 + 0, gA,     aA);
            storeTask(coln, lane, warp * 8 + 1, gA + 4, aA + 4);
            gatherTask(dxB[0], dyB[0], mB[0], kyf, kxf, pbase + 2, xb, gB,     aB);
            gatherTask(dxB[1], dyB[1], mB[1], kyf, kxf, pbase + 3, xb, gB + 4, aB + 4);
            dxA[0] = offx[4]; dyA[0] = offy[4]; mA[0] = mk[4];
            dxA[1] = offx[5]; dyA[1] = offy[5]; mA[1] = mk[5];
        }
        GEMM_CHUNK(2);
        if (pre) {
            storeTask(coln, lane, warp * 8 + 2, gB,     aB);
            storeTask(coln, lane, warp * 8 + 3, gB + 4, aB + 4);
            gatherTask(dxA[0], dyA[0], mA[0], kyf, kxf, pbase + 4, xb, gA,     aA);
            gatherTask(dxA[1], dyA[1], mA[1], kyf, kxf, pbase + 5, xb, gA + 4, aA + 4);
            dxB[0] = offx[6]; dyB[0] = offy[6]; mB[0] = mk[6];
            dxB[1] = offx[7]; dyB[1] = offy[7]; mB[1] = mk[7];
        }
        GEMM_CHUNK(3);
        if (pre) {
            storeTask(coln, lane, warp * 8 + 4, gA,     aA);
            storeTask(coln, lane, warp * 8 + 5, gA + 4, aA + 4);
            gatherTask(dxB[0], dyB[0], mB[0], kyf, kxf, pbase + 6, xb, gB,     aB);
            gatherTask(dxB[1], dyB[1], mB[1], kyf, kxf, pbase + 7, xb, gB + 4, aB + 4);
            storeTask(coln, lane, warp * 8 + 6, gB,     aB);
            storeTask(coln, lane, warp * 8 + 7, gB + 4, aB + 4);
            CP_WAIT0();
        }
        __syncthreads();
        #undef GEMM_CHUNK
    }

    // ---- epilogue: reduce channel halves, add bias, store ----
    #pragma unroll
    for (int oi = 0; oi < 4; oi++) {
        const int o = o0 + oi;
        const float bo = bias[o];
        float* op = out + (((size_t)b * COUT + o) * HH + h) * WW + w0 + pg;
        #pragma unroll
        for (int i = 0; i < 4; i++)
            op[16 * i] = lo32(acc[i][oi]) + hi32(acc[i][oi]) + bo;
    }
}

extern "C" void kernel_launch(void* const* d_in, const int* in_sizes, int n_in,
                              void* d_out, int out_size) {
    const float* x      = (const float*)d_in[0];
    const float* offset = (const float*)d_in[1];
    const float* mask   = (const float*)d_in[2];
    const float* weight = (const float*)d_in[3];
    const float* bias   = (const float*)d_in[4];
    float* out = (float*)d_out;

    const int smem = (2 * CBUF + 2 * WBUF) * (int)sizeof(float);  // 66048 B
    cudaFuncSetAttribute(k_dcn_main, cudaFuncAttributeMaxDynamicSharedMemorySize, smem);

    k_transpose_x<<<NPIX / 32, 256>>>(x);
    k_prep_w<<<(K2 * 32 * COUT * 2 + 255) / 256, 256>>>(weight);
    k_dcn_main<<<BB * HH * (WW / PT), 256, smem>>>(offset, mask, bias, out);
}

// round 6
// speedup vs baseline: 2.4133x; 1.1612x over previous
#include <cuda_runtime.h>

#define BB   8
#define CC   64
#define HH   128
#define WW   128
#define COUT 64
#define K2   9
#define HWSZ (HH*WW)        /* 16384 */
#define NPIX (BB*HWSZ)      /* 131072 */
#define PT   64             /* pixel tile per block */
#define PITCH 130           /* 2*PT + 2 pad */
#define CBUF (32*PITCH)     /* 4160 floats per col buffer */
#define WBUF 4096           /* floats per weight buffer (32 rows x 128) */
#define WOFF (2*CBUF)       /* 8320 */

typedef unsigned long long u64;

// scratch (allocation-free rule: __device__ globals)
__device__ __align__(16) float g_xt[(size_t)NPIX * CC];   // x in NHWC, 33.5 MB
__device__ __align__(16) float g_wt[K2 * 32 * COUT * 2];  // weights packed: [k*32+pair][o][2]

__device__ __forceinline__ u64 fma2(u64 a, u64 b, u64 c) {
    u64 d;
    asm("fma.rn.f32x2 %0, %1, %2, %3;" : "=l"(d) : "l"(a), "l"(b), "l"(c));
    return d;
}
__device__ __forceinline__ float lo32(u64 v) { return __uint_as_float((unsigned)v); }
__device__ __forceinline__ float hi32(u64 v) { return __uint_as_float((unsigned)(v >> 32)); }

__device__ __forceinline__ void cp16(void* s, const void* g) {
    unsigned a = (unsigned)__cvta_generic_to_shared(s);
    asm volatile("cp.async.cg.shared.global [%0], [%1], 16;\n" :: "r"(a), "l"(g) : "memory");
}
#define CP_COMMIT() asm volatile("cp.async.commit_group;\n" ::: "memory")
#define CP_WAIT0()  asm volatile("cp.async.wait_group 0;\n" ::: "memory")

// ---------------- kernel 1: NCHW -> NHWC transpose of x ----------------
__global__ __launch_bounds__(256) void k_transpose_x(const float* __restrict__ x) {
    __shared__ float s[64][33];
    const int tile = blockIdx.x;
    const int px0  = tile * 32;
    const int b    = px0 >> 14;
    const int pix0 = px0 & 16383;
    const int t    = threadIdx.x;
    const int lane = t & 31;
    const int cg   = t >> 5;
    #pragma unroll
    for (int cc = cg; cc < 64; cc += 8)
        s[cc][lane] = x[((size_t)(b * 64 + cc)) * HWSZ + pix0 + lane];
    __syncthreads();
    #pragma unroll
    for (int i = t; i < 2048; i += 256) {
        int c = i & 63;
        int p = i >> 6;
        g_xt[((size_t)(px0 + p)) * CC + c] = s[c][p];
    }
}

// ---------------- kernel 2: pack weights as channel pairs ----------------
__global__ __launch_bounds__(256) void k_prep_w(const float* __restrict__ w) {
    int i = blockIdx.x * 256 + threadIdx.x;
    if (i < K2 * 32 * COUT * 2) {
        int j = i & 1;
        int o = (i >> 1) & 63;
        int r = i >> 7;
        int c = 2 * (r & 31) + j;
        int k = r >> 5;
        g_wt[i] = w[(o * 64 + c) * 9 + k];
    }
}

// ---------------- producer helpers ----------------
__device__ __forceinline__ void sampleTask(
    float dx, float dy, float m, float kyf, float kxf, int px_coord,
    const float* __restrict__ xb, float2 g[4], float a[4])
{
    const float py  = kyf + dy;
    const float px  = (float)(px_coord - 1) + kxf + dx;
    const float y0f = floorf(py), x0f = floorf(px);
    const float wy1 = py - y0f,  wx1 = px - x0f;
    const float wy0 = 1.f - wy1, wx0 = 1.f - wx1;
    const int iy = (int)y0f, ix = (int)x0f;
    const bool vy0 = (unsigned)iy < (unsigned)HH, vy1 = (unsigned)(iy + 1) < (unsigned)HH;
    const bool vx0 = (unsigned)ix < (unsigned)WW, vx1 = (unsigned)(ix + 1) < (unsigned)WW;
    const float2 z = make_float2(0.f, 0.f);
    const float* bp = xb + ((long)iy * WW + ix) * CC;
    g[0] = (vy0 && vx0) ? *(const float2*)(bp)               : z;
    g[1] = (vy0 && vx1) ? *(const float2*)(bp + CC)          : z;
    g[2] = (vy1 && vx0) ? *(const float2*)(bp + WW * CC)     : z;
    g[3] = (vy1 && vx1) ? *(const float2*)(bp + WW * CC + CC): z;
    a[0] = m * wy0 * wx0;
    a[1] = m * wy0 * wx1;
    a[2] = m * wy1 * wx0;
    a[3] = m * wy1 * wx1;
}

__device__ __forceinline__ void storeTask(
    float* __restrict__ colb, int lane, int plocal, const float2 g[4], const float a[4])
{
    float2 v;
    v.x = a[0] * g[0].x + a[1] * g[1].x + a[2] * g[2].x + a[3] * g[3].x;
    v.y = a[0] * g[0].y + a[1] * g[1].y + a[2] * g[2].y + a[3] * g[3].y;
    *(float2*)(colb + lane * PITCH + 2 * plocal) = v;
}

// sample one tap (16 tasks) for producer warp s into coln; one-group lookahead pipeline
__device__ __forceinline__ void sampleTap(
    int kn, int h, int pbase, const float* __restrict__ offb,
    const float* __restrict__ mb, const float* __restrict__ xb,
    float* __restrict__ coln, int lane, int s)
{
    const int   kny = kn / 3;
    const float kyf = (float)(h - 1 + kny);
    const float kxf = (float)(kn - 3 * kny);
    const float* offx = offb + (size_t)(2 * kn) * HWSZ;
    const float* offy = offx + HWSZ;
    const float* mk   = mb + (size_t)kn * HWSZ;
    const int p0 = s * 16;

    float2 g[4][4];
    float  a[4][4];
    #pragma unroll
    for (int j = 0; j < 4; j++)
        sampleTask(offx[j], offy[j], mk[j], kyf, kxf, pbase + j, xb, g[j], a[j]);

    #pragma unroll
    for (int grp = 0; grp < 4; grp++) {
        float2 gn[4][4];
        float  an[4][4];
        if (grp < 3) {
            #pragma unroll
            for (int j = 0; j < 4; j++) {
                const int tt = (grp + 1) * 4 + j;
                sampleTask(offx[tt], offy[tt], mk[tt], kyf, kxf, pbase + tt, xb, gn[j], an[j]);
            }
        }
        #pragma unroll
        for (int j = 0; j < 4; j++)
            storeTask(coln, lane, p0 + grp * 4 + j, g[j], a[j]);
        if (grp < 3) {
            #pragma unroll
            for (int j = 0; j < 4; j++) {
                #pragma unroll
                for (int q = 0; q < 4; q++) { g[j][q] = gn[j][q]; a[j][q] = an[j][q]; }
            }
        }
    }
}

// ---------------- kernel 3: warp-specialized fused kernel ----------------
__global__ __launch_bounds__(256, 2) void k_dcn_main(
    const float* __restrict__ offset, const float* __restrict__ mask,
    const float* __restrict__ bias, float* __restrict__ out)
{
    extern __shared__ float smem[];   // [2*CBUF col | 2*WBUF weights]
    const int t    = threadIdx.x;
    const int lane = t & 31;
    const int warp = t >> 5;          // 0..3 consumers, 4..7 producers
    const int blk  = blockIdx.x;
    const int w0   = (blk & 1) * PT;
    const int h    = (blk >> 1) & 127;
    const int b    = blk >> 8;

    if (warp >= 4) {
        // ================= PRODUCER =================
        const int s  = warp - 4;
        const int ts = t - 128;
        const int pbase = w0 + s * 16;
        const float* offb = offset + ((size_t)b * 18 * HH + h) * WW + pbase;
        const float* mb   = mask   + ((size_t)b *  9 * HH + h) * WW + pbase;
        const float* xb   = g_xt + (size_t)b * HWSZ * CC + lane * 2;

        {   // prologue: tap-0 weights + samples into buffer 0
            float4* wd = (float4*)(smem + WOFF);
            const float4* ws = (const float4*)g_wt;
            #pragma unroll
            for (int i = 0; i < 8; i++)
                cp16(wd + ts + i * 128, ws + ts + i * 128);
            CP_COMMIT();
            sampleTap(0, h, pbase, offb, mb, xb, smem, lane, s);
            CP_WAIT0();
        }
        __syncthreads();

        #pragma unroll 1
        for (int k = 0; k < K2; k++) {
            if (k < K2 - 1) {
                const int kn  = k + 1;
                const int nxt = kn & 1;
                float4* wd = (float4*)(smem + WOFF + nxt * WBUF);
                const float4* ws = (const float4*)(g_wt + (size_t)kn * WBUF);
                #pragma unroll
                for (int i = 0; i < 8; i++)
                    cp16(wd + ts + i * 128, ws + ts + i * 128);
                CP_COMMIT();
                sampleTap(kn, h, pbase, offb, mb, xb, smem + nxt * CBUF, lane, s);
                CP_WAIT0();
            }
            __syncthreads();
        }
    } else {
        // ================= CONSUMER =================
        const int pg = lane & 15;
        const int o0 = (warp * 2 + (lane >> 4)) * 8;
        u64 acc[4][8];
        #pragma unroll
        for (int i = 0; i < 4; i++)
            #pragma unroll
            for (int j = 0; j < 8; j++) acc[i][j] = 0ull;

        __syncthreads();   // matches producer prologue barrier

        #pragma unroll 1
        for (int k = 0; k < K2; k++) {
            const int cur = k & 1;
            const float* colc = smem + cur * CBUF + 2 * pg;
            const u64*   wb   = (const u64*)(smem + WOFF + cur * WBUF) + o0;
            #pragma unroll 4
            for (int r = 0; r < 32; r++) {
                const float* cs = colc + r * PITCH;
                u64 cc0 = *(const u64*)(cs);
                u64 cc1 = *(const u64*)(cs + 32);
                u64 cc2 = *(const u64*)(cs + 64);
                u64 cc3 = *(const u64*)(cs + 96);
                const ulonglong2* wp = (const ulonglong2*)(wb + (size_t)r * 64);
                ulonglong2 w01 = wp[0];
                ulonglong2 w23 = wp[1];
                ulonglong2 w45 = wp[2];
                ulonglong2 w67 = wp[3];
                acc[0][0] = fma2(cc0, w01.x, acc[0][0]);
                acc[1][0] = fma2(cc1, w01.x, acc[1][0]);
                acc[2][0] = fma2(cc2, w01.x, acc[2][0]);
                acc[3][0] = fma2(cc3, w01.x, acc[3][0]);
                acc[0][1] = fma2(cc0, w01.y, acc[0][1]);
                acc[1][1] = fma2(cc1, w01.y, acc[1][1]);
                acc[2][1] = fma2(cc2, w01.y, acc[2][1]);
                acc[3][1] = fma2(cc3, w01.y, acc[3][1]);
                acc[0][2] = fma2(cc0, w23.x, acc[0][2]);
                acc[1][2] = fma2(cc1, w23.x, acc[1][2]);
                acc[2][2] = fma2(cc2, w23.x, acc[2][2]);
                acc[3][2] = fma2(cc3, w23.x, acc[3][2]);
                acc[0][3] = fma2(cc0, w23.y, acc[0][3]);
                acc[1][3] = fma2(cc1, w23.y, acc[1][3]);
                acc[2][3] = fma2(cc2, w23.y, acc[2][3]);
                acc[3][3] = fma2(cc3, w23.y, acc[3][3]);
                acc[0][4] = fma2(cc0, w45.x, acc[0][4]);
                acc[1][4] = fma2(cc1, w45.x, acc[1][4]);
                acc[2][4] = fma2(cc2, w45.x, acc[2][4]);
                acc[3][4] = fma2(cc3, w45.x, acc[3][4]);
                acc[0][5] = fma2(cc0, w45.y, acc[0][5]);
                acc[1][5] = fma2(cc1, w45.y, acc[1][5]);
                acc[2][5] = fma2(cc2, w45.y, acc[2][5]);
                acc[3][5] = fma2(cc3, w45.y, acc[3][5]);
                acc[0][6] = fma2(cc0, w67.x, acc[0][6]);
                acc[1][6] = fma2(cc1, w67.x, acc[1][6]);
                acc[2][6] = fma2(cc2, w67.x, acc[2][6]);
                acc[3][6] = fma2(cc3, w67.x, acc[3][6]);
                acc[0][7] = fma2(cc0, w67.y, acc[0][7]);
                acc[1][7] = fma2(cc1, w67.y, acc[1][7]);
                acc[2][7] = fma2(cc2, w67.y, acc[2][7]);
                acc[3][7] = fma2(cc3, w67.y, acc[3][7]);
            }
            __syncthreads();
        }

        #pragma unroll
        for (int oi = 0; oi < 8; oi++) {
            const int o = o0 + oi;
            const float bo = __ldg(bias + o);
            float* op = out + (((size_t)b * COUT + o) * HH + h) * WW + w0 + pg;
            #pragma unroll
            for (int i = 0; i < 4; i++)
                op[16 * i] = lo32(acc[i][oi]) + hi32(acc[i][oi]) + bo;
        }
    }
}

extern "C" void kernel_launch(void* const* d_in, const int* in_sizes, int n_in,
                              void* d_out, int out_size) {
    const float* x      = (const float*)d_in[0];
    const float* offset = (const float*)d_in[1];
    const float* mask   = (const float*)d_in[2];
    const float* weight = (const float*)d_in[3];
    const float* bias   = (const float*)d_in[4];
    float* out = (float*)d_out;

    const int smem = (2 * CBUF + 2 * WBUF) * (int)sizeof(float);  // 66048 B
    cudaFuncSetAttribute(k_dcn_main, cudaFuncAttributeMaxDynamicSharedMemorySize, smem);

    k_transpose_x<<<NPIX / 32, 256>>>(x);
    k_prep_w<<<(K2 * 32 * COUT * 2 + 255) / 256, 256>>>(weight);
    k_dcn_main<<<BB * HH * (WW / PT), 256, smem>>>(offset, mask, bias, out);
}